// round 16
// baseline (speedup 1.0000x reference)
#include <cuda_runtime.h>
#include <cstdint>
#include <math.h>

#define NUM_LEVELS 16
#define TABLE_SIZE (1u << 20)
#define TMASK (TABLE_SIZE - 1u)
#define P2 2654435761u
#define P3 805459861u

#define CAP (1 << 21)
#define GRES 128                        // Morton bucket grid resolution
#define NB  (GRES * GRES * GRES)        // 2,097,152 buckets
#define SCAN_BLOCK 1024
#define SCAN_GRID  (NB / SCAN_BLOCK)    // 2048

__device__ int g_cnt[NB];
__device__ int g_off[NB];      // local (per-scan-block) exclusive scan
__device__ int g_aux[SCAN_GRID];
__device__ int g_keys[CAP];
__device__ int g_rank[CAP];
__device__ int g_perm[CAP];

struct ResParams {
    int res[NUM_LEVELS];
};

// ---------------- sorting kernels ----------------

__device__ __forceinline__ uint32_t spread3(uint32_t x) {
    x &= 0x3FFu;
    x = (x | (x << 16)) & 0x030000FFu;
    x = (x | (x << 8))  & 0x0300F00Fu;
    x = (x | (x << 4))  & 0x030C30C3u;
    x = (x | (x << 2))  & 0x09249249u;
    return x;
}

__global__ void k_zero() {
    int i = blockIdx.x * blockDim.x + threadIdx.x;
    if (i * 4 < NB) {
        *(int4*)(g_cnt + i * 4) = make_int4(0, 0, 0, 0);
    }
}

// Histogram; atomicAdd's return value doubles as the point's rank within
// its bucket, making the scatter pass atomic-free.
__global__ void k_hist(const float* __restrict__ pos, int n) {
    int i = blockIdx.x * blockDim.x + threadIdx.x;
    if (i >= n) return;
    float px = fminf(fmaxf(pos[3 * i + 0], 0.0f), 1.0f);
    float py = fminf(fmaxf(pos[3 * i + 1], 0.0f), 1.0f);
    float pz = fminf(fmaxf(pos[3 * i + 2], 0.0f), 1.0f);
    int cx = min((int)(px * (float)GRES), GRES - 1);
    int cy = min((int)(py * (float)GRES), GRES - 1);
    int cz = min((int)(pz * (float)GRES), GRES - 1);
    uint32_t key = spread3((uint32_t)cx) | (spread3((uint32_t)cy) << 1)
                 | (spread3((uint32_t)cz) << 2);
    g_keys[i] = (int)key;
    g_rank[i] = atomicAdd(&g_cnt[key], 1);
}

// Local exclusive scan of g_cnt -> g_off, block total -> g_aux.
__global__ void k_scan1() {
    __shared__ int sh[SCAN_BLOCK];
    int t = threadIdx.x;
    int idx = blockIdx.x * SCAN_BLOCK + t;
    int v = g_cnt[idx];
    sh[t] = v;
    __syncthreads();
    for (int d = 1; d < SCAN_BLOCK; d <<= 1) {
        int x = (t >= d) ? sh[t - d] : 0;
        __syncthreads();
        sh[t] += x;
        __syncthreads();
    }
    g_off[idx] = sh[t] - v;                               // local exclusive
    if (t == SCAN_BLOCK - 1) g_aux[blockIdx.x] = sh[t];   // block total
}

// Exclusive scan of the 2048 block totals (2 elements per thread).
__global__ void k_scan2() {
    __shared__ int sh[SCAN_GRID / 2];   // 1024 pair-sums
    int t = threadIdx.x;                // 0..1023
    int a0 = g_aux[2 * t];
    int a1 = g_aux[2 * t + 1];
    int pair = a0 + a1;
    sh[t] = pair;
    __syncthreads();
    for (int d = 1; d < SCAN_GRID / 2; d <<= 1) {
        int x = (t >= d) ? sh[t - d] : 0;
        __syncthreads();
        sh[t] += x;
        __syncthreads();
    }
    int excl = sh[t] - pair;            // exclusive pair-scan
    g_aux[2 * t]     = excl;
    g_aux[2 * t + 1] = excl + a0;
}

// Atomic-free scatter: dst = local offset + scan-block base + rank.
__global__ void k_scatter(int n) {
    int i = blockIdx.x * blockDim.x + threadIdx.x;
    if (i >= n) return;
    int key = g_keys[i];
    int dst = g_off[key] + g_aux[key >> 10] + g_rank[i];
    g_perm[dst] = i;
}

// ---------------- main kernel (R12/R14 winner, unchanged) ----------------

__device__ __forceinline__ void load_pair(const float2* __restrict__ tl,
                                          uint32_t hm,
                                          float2& f0, float2& f1)
{
    uint32_t base = hm & ~1u;
    float4 v = __ldg((const float4*)(tl + base));
    bool odd = (hm & 1u) != 0u;

    float2 fix;
    fix.x = v.z; fix.y = v.w;
    if (odd) {
        fix = __ldg(tl + ((hm + 1u) & TMASK));
    }
    f0.x = odd ? v.z : v.x;
    f0.y = odd ? v.w : v.y;
    f1.x = odd ? fix.x : v.z;
    f1.y = odd ? fix.y : v.w;
}

// Block = 16 Morton-sorted points, 128 threads; thread handles 2 levels.
__global__ __launch_bounds__(128)
void k_main(const float* __restrict__ pos,
            const float* __restrict__ tables,
            float* __restrict__ out,
            int n_points,
            ResParams rp,
            int use_perm)
{
    __shared__ int   s_pid[16];
    __shared__ float s_pos[16][3];
    __shared__ float s_out[16][34];   // padded to kill bank conflicts

    int tid = threadIdx.x;
    long long base = (long long)blockIdx.x * 16;

    if (tid < 16) {
        long long s = base + tid;
        int pid = -1;
        if (s < n_points) pid = use_perm ? g_perm[s] : (int)s;
        s_pid[tid] = pid;
        int pld = (pid >= 0) ? pid : 0;
        s_pos[tid][0] = __ldg(pos + 3 * pld + 0);
        s_pos[tid][1] = __ldg(pos + 3 * pld + 1);
        s_pos[tid][2] = __ldg(pos + 3 * pld + 2);
    }
    __syncthreads();

    int p  = tid & 15;
    int pr = tid >> 4;   // 0..7  -> levels pr and pr+8

    float px = fminf(fmaxf(s_pos[p][0], 0.0f), 1.0f);
    float py = fminf(fmaxf(s_pos[p][1], 0.0f), 1.0f);
    float pz = fminf(fmaxf(s_pos[p][2], 0.0f), 1.0f);

#pragma unroll
    for (int half = 0; half < 2; half++) {
        int lvl = pr + half * 8;
        int res_i = rp.res[lvl];
        float res = (float)res_i;

        float sx = px * res, sy = py * res, sz = pz * res;
        float fx = floorf(sx), fy = floorf(sy), fz = floorf(sz);
        float tx = sx - fx, ty = sy - fy, tz = sz - fz;

        int r1 = res_i - 1;
        int cx = min(max((int)fx, 0), r1);
        int cy = min(max((int)fy, 0), r1);
        int cz = min(max((int)fz, 0), r1);

        uint32_t h0 = (uint32_t)cx + (uint32_t)cy * P2 + (uint32_t)cz * P3;

        const float2* __restrict__ tl =
            (const float2*)tables + (size_t)lvl * TABLE_SIZE;

        float2 f000, f100, f001, f101, f010, f110, f011, f111;
        load_pair(tl, (h0)           & TMASK, f000, f100);
        load_pair(tl, (h0 + P3)      & TMASK, f001, f101);
        load_pair(tl, (h0 + P2)      & TMASK, f010, f110);
        load_pair(tl, (h0 + P2 + P3) & TMASK, f011, f111);

        // Reference blend, bit-exact (tx pairs k, ty pairs i, tz pairs j):
        float wx0 = 1.0f - tx, wy0 = 1.0f - ty, wz0 = 1.0f - tz;

        float c00x = f000.x * wx0 + f001.x * tx;
        float c00y = f000.y * wx0 + f001.y * tx;
        float c01x = f010.x * wx0 + f011.x * tx;
        float c01y = f010.y * wx0 + f011.y * tx;
        float c10x = f100.x * wx0 + f101.x * tx;
        float c10y = f100.y * wx0 + f101.y * tx;
        float c11x = f110.x * wx0 + f111.x * tx;
        float c11y = f110.y * wx0 + f111.y * tx;

        float c0x = c00x * wy0 + c10x * ty;
        float c0y = c00y * wy0 + c10y * ty;
        float c1x = c01x * wy0 + c11x * ty;
        float c1y = c01y * wy0 + c11y * ty;

        s_out[p][2 * lvl]     = c0x * wz0 + c1x * tz;
        s_out[p][2 * lvl + 1] = c0y * wz0 + c1y * tz;
    }

    __syncthreads();

    // write-out: 128 threads store 16 lines x 16 float2 (2 slots each)
#pragma unroll
    for (int half = 0; half < 2; half++) {
        int slot = tid + half * 128;      // 0..255
        int q = slot >> 4;
        int w = slot & 15;
        int qpid = s_pid[q];
        if (qpid >= 0) {
            float2 v = make_float2(s_out[q][2 * w], s_out[q][2 * w + 1]);
            __stcs((float2*)(out + (size_t)qpid * 32) + w, v);
        }
    }
}

extern "C" void kernel_launch(void* const* d_in, const int* in_sizes, int n_in,
                              void* d_out, int out_size)
{
    const float* positions = (const float*)d_in[0];
    const float* tables    = (const float*)d_in[1];
    float* out             = (float*)d_out;

    int n_points = in_sizes[0] / 3;

    ResParams rp;
    {
        double b = exp(log(2048.0 / 16.0) / 15.0);
        for (int l = 0; l < NUM_LEVELS; l++) {
            rp.res[l] = (int)(16.0 * pow(b, (double)l));
        }
    }

    int use_perm = (n_points <= CAP) ? 1 : 0;

    if (use_perm) {
        k_zero<<<(NB / 4 + 255) / 256, 256>>>();
        k_hist<<<(n_points + 511) / 512, 512>>>(positions, n_points);
        k_scan1<<<SCAN_GRID, SCAN_BLOCK>>>();
        k_scan2<<<1, SCAN_GRID / 2>>>();
        k_scatter<<<(n_points + 511) / 512, 512>>>(n_points);
    }

    long long nblocks = ((long long)n_points + 15) / 16;
    k_main<<<(unsigned)nblocks, 128>>>(positions, tables, out,
                                       n_points, rp, use_perm);
}

// round 17
// speedup vs baseline: 1.0352x; 1.0352x over previous
#include <cuda_runtime.h>
#include <cstdint>
#include <math.h>

#define NUM_LEVELS 16
#define TABLE_SIZE (1u << 20)
#define TMASK (TABLE_SIZE - 1u)
#define P2 2654435761u
#define P3 805459861u

#define CAP (1 << 21)
#define GRES 64                         // Morton bucket grid (R15 winner)
#define NB  (GRES * GRES * GRES)        // 262144 buckets
#define SCAN_BLOCK 1024
#define SCAN_GRID  (NB / SCAN_BLOCK)    // 256

__device__ int g_cnt[NB];
__device__ int g_off[NB];      // local (per-scan-block) exclusive scan
__device__ int g_aux[SCAN_GRID];
__device__ unsigned g_kr[CAP]; // packed: key<<13 | rank
__device__ int g_perm[CAP];

struct ResParams {
    int res[NUM_LEVELS];
};

// ---------------- sorting kernels ----------------

__device__ __forceinline__ uint32_t spread3(uint32_t x) {
    x &= 0x3FFu;
    x = (x | (x << 16)) & 0x030000FFu;
    x = (x | (x << 8))  & 0x0300F00Fu;
    x = (x | (x << 4))  & 0x030C30C3u;
    x = (x | (x << 2))  & 0x09249249u;
    return x;
}

__global__ void k_zero() {
    int i = blockIdx.x * blockDim.x + threadIdx.x;
    if (i * 4 < NB) {
        *(int4*)(g_cnt + i * 4) = make_int4(0, 0, 0, 0);
    }
}

// Histogram; atomicAdd's return doubles as the point's rank within its
// bucket (packed with the key -> scatter is atomic-free, one array only).
__global__ void k_hist(const float* __restrict__ pos, int n) {
    int i = blockIdx.x * blockDim.x + threadIdx.x;
    if (i >= n) return;
    float px = fminf(fmaxf(pos[3 * i + 0], 0.0f), 1.0f);
    float py = fminf(fmaxf(pos[3 * i + 1], 0.0f), 1.0f);
    float pz = fminf(fmaxf(pos[3 * i + 2], 0.0f), 1.0f);
    int cx = min((int)(px * (float)GRES), GRES - 1);
    int cy = min((int)(py * (float)GRES), GRES - 1);
    int cz = min((int)(pz * (float)GRES), GRES - 1);
    uint32_t key = spread3((uint32_t)cx) | (spread3((uint32_t)cy) << 1)
                 | (spread3((uint32_t)cz) << 2);
    unsigned rank = (unsigned)atomicAdd(&g_cnt[key], 1);
    g_kr[i] = (key << 13) | (rank & 0x1FFFu);
}

// Local exclusive scan of g_cnt -> g_off, block total -> g_aux.
__global__ void k_scan1() {
    __shared__ int sh[SCAN_BLOCK];
    int t = threadIdx.x;
    int idx = blockIdx.x * SCAN_BLOCK + t;
    int v = g_cnt[idx];
    sh[t] = v;
    __syncthreads();
    for (int d = 1; d < SCAN_BLOCK; d <<= 1) {
        int x = (t >= d) ? sh[t - d] : 0;
        __syncthreads();
        sh[t] += x;
        __syncthreads();
    }
    g_off[idx] = sh[t] - v;                               // local exclusive
    if (t == SCAN_BLOCK - 1) g_aux[blockIdx.x] = sh[t];   // block total
}

// Exclusive scan of the 256 block totals.
__global__ void k_scan2() {
    __shared__ int sh[SCAN_GRID];
    int t = threadIdx.x;
    int v = g_aux[t];
    sh[t] = v;
    __syncthreads();
    for (int d = 1; d < SCAN_GRID; d <<= 1) {
        int x = (t >= d) ? sh[t - d] : 0;
        __syncthreads();
        sh[t] += x;
        __syncthreads();
    }
    g_aux[t] = sh[t] - v;
}

// Atomic-free scatter: dst = local offset + scan-block base + rank.
__global__ void k_scatter(int n) {
    int i = blockIdx.x * blockDim.x + threadIdx.x;
    if (i >= n) return;
    unsigned kr = g_kr[i];
    unsigned key = kr >> 13;
    unsigned rank = kr & 0x1FFFu;
    int dst = g_off[key] + g_aux[key >> 10] + (int)rank;
    g_perm[dst] = i;
}

// ---------------- main kernel (R12/R14 winner, unchanged) ----------------

__device__ __forceinline__ void load_pair(const float2* __restrict__ tl,
                                          uint32_t hm,
                                          float2& f0, float2& f1)
{
    uint32_t base = hm & ~1u;
    float4 v = __ldg((const float4*)(tl + base));
    bool odd = (hm & 1u) != 0u;

    float2 fix;
    fix.x = v.z; fix.y = v.w;
    if (odd) {
        fix = __ldg(tl + ((hm + 1u) & TMASK));
    }
    f0.x = odd ? v.z : v.x;
    f0.y = odd ? v.w : v.y;
    f1.x = odd ? fix.x : v.z;
    f1.y = odd ? fix.y : v.w;
}

// Block = 16 Morton-sorted points, 128 threads; thread handles 2 levels.
__global__ __launch_bounds__(128)
void k_main(const float* __restrict__ pos,
            const float* __restrict__ tables,
            float* __restrict__ out,
            int n_points,
            ResParams rp,
            int use_perm)
{
    __shared__ int   s_pid[16];
    __shared__ float s_pos[16][3];
    __shared__ float s_out[16][34];   // padded to kill bank conflicts

    int tid = threadIdx.x;
    long long base = (long long)blockIdx.x * 16;

    if (tid < 16) {
        long long s = base + tid;
        int pid = -1;
        if (s < n_points) pid = use_perm ? g_perm[s] : (int)s;
        s_pid[tid] = pid;
        int pld = (pid >= 0) ? pid : 0;
        s_pos[tid][0] = __ldg(pos + 3 * pld + 0);
        s_pos[tid][1] = __ldg(pos + 3 * pld + 1);
        s_pos[tid][2] = __ldg(pos + 3 * pld + 2);
    }
    __syncthreads();

    int p  = tid & 15;
    int pr = tid >> 4;   // 0..7  -> levels pr and pr+8

    float px = fminf(fmaxf(s_pos[p][0], 0.0f), 1.0f);
    float py = fminf(fmaxf(s_pos[p][1], 0.0f), 1.0f);
    float pz = fminf(fmaxf(s_pos[p][2], 0.0f), 1.0f);

#pragma unroll
    for (int half = 0; half < 2; half++) {
        int lvl = pr + half * 8;
        int res_i = rp.res[lvl];
        float res = (float)res_i;

        float sx = px * res, sy = py * res, sz = pz * res;
        float fx = floorf(sx), fy = floorf(sy), fz = floorf(sz);
        float tx = sx - fx, ty = sy - fy, tz = sz - fz;

        int r1 = res_i - 1;
        int cx = min(max((int)fx, 0), r1);
        int cy = min(max((int)fy, 0), r1);
        int cz = min(max((int)fz, 0), r1);

        uint32_t h0 = (uint32_t)cx + (uint32_t)cy * P2 + (uint32_t)cz * P3;

        const float2* __restrict__ tl =
            (const float2*)tables + (size_t)lvl * TABLE_SIZE;

        float2 f000, f100, f001, f101, f010, f110, f011, f111;
        load_pair(tl, (h0)           & TMASK, f000, f100);
        load_pair(tl, (h0 + P3)      & TMASK, f001, f101);
        load_pair(tl, (h0 + P2)      & TMASK, f010, f110);
        load_pair(tl, (h0 + P2 + P3) & TMASK, f011, f111);

        // Reference blend, bit-exact (tx pairs k, ty pairs i, tz pairs j):
        float wx0 = 1.0f - tx, wy0 = 1.0f - ty, wz0 = 1.0f - tz;

        float c00x = f000.x * wx0 + f001.x * tx;
        float c00y = f000.y * wx0 + f001.y * tx;
        float c01x = f010.x * wx0 + f011.x * tx;
        float c01y = f010.y * wx0 + f011.y * tx;
        float c10x = f100.x * wx0 + f101.x * tx;
        float c10y = f100.y * wx0 + f101.y * tx;
        float c11x = f110.x * wx0 + f111.x * tx;
        float c11y = f110.y * wx0 + f111.y * tx;

        float c0x = c00x * wy0 + c10x * ty;
        float c0y = c00y * wy0 + c10y * ty;
        float c1x = c01x * wy0 + c11x * ty;
        float c1y = c01y * wy0 + c11y * ty;

        s_out[p][2 * lvl]     = c0x * wz0 + c1x * tz;
        s_out[p][2 * lvl + 1] = c0y * wz0 + c1y * tz;
    }

    __syncthreads();

    // write-out: 128 threads store 16 lines x 16 float2 (2 slots each)
#pragma unroll
    for (int half = 0; half < 2; half++) {
        int slot = tid + half * 128;      // 0..255
        int q = slot >> 4;
        int w = slot & 15;
        int qpid = s_pid[q];
        if (qpid >= 0) {
            float2 v = make_float2(s_out[q][2 * w], s_out[q][2 * w + 1]);
            __stcs((float2*)(out + (size_t)qpid * 32) + w, v);
        }
    }
}

extern "C" void kernel_launch(void* const* d_in, const int* in_sizes, int n_in,
                              void* d_out, int out_size)
{
    const float* positions = (const float*)d_in[0];
    const float* tables    = (const float*)d_in[1];
    float* out             = (float*)d_out;

    int n_points = in_sizes[0] / 3;

    ResParams rp;
    {
        double b = exp(log(2048.0 / 16.0) / 15.0);
        for (int l = 0; l < NUM_LEVELS; l++) {
            rp.res[l] = (int)(16.0 * pow(b, (double)l));
        }
    }

    int use_perm = (n_points <= CAP) ? 1 : 0;

    if (use_perm) {
        k_zero<<<(NB / 4 + 255) / 256, 256>>>();
        k_hist<<<(n_points + 511) / 512, 512>>>(positions, n_points);
        k_scan1<<<SCAN_GRID, SCAN_BLOCK>>>();
        k_scan2<<<1, SCAN_GRID>>>();
        k_scatter<<<(n_points + 511) / 512, 512>>>(n_points);
    }

    long long nblocks = ((long long)n_points + 15) / 16;
    k_main<<<(unsigned)nblocks, 128>>>(positions, tables, out,
                                       n_points, rp, use_perm);
}